// round 1
// baseline (speedup 1.0000x reference)
#include <cuda_runtime.h>
#include <math.h>

#define B_ 2
#define S_ 4096
#define DM_ 512
#define H_ 8
#define D_ 64
#define BS_ 64
#define NB_ 64
#define R_ 3
#define MROWS (B_*S_)   /* 8192 */
#define NC (H_*D_)      /* 512  */

// Scratch for projected Q/K/V in [B*S, H*D] layout (16 MB each).
__device__ float g_q[MROWS * NC];
__device__ float g_k[MROWS * NC];
__device__ float g_v[MROWS * NC];

// ---------------------------------------------------------------------------
// Kernel 1: fused QKV projection. grid = (M/128, 512/128, 3), 256 threads.
// C = X @ W + b  with 128x128 block tile, BK=8, 8x8 register tile per thread.
// ---------------------------------------------------------------------------
__global__ __launch_bounds__(256) void qkv_gemm(
    const float* __restrict__ x,
    const float* __restrict__ wq, const float* __restrict__ bq,
    const float* __restrict__ wk, const float* __restrict__ bk,
    const float* __restrict__ wv, const float* __restrict__ bv)
{
    const float* W; const float* bias; float* out;
    if (blockIdx.z == 0)      { W = wq; bias = bq; out = g_q; }
    else if (blockIdx.z == 1) { W = wk; bias = bk; out = g_k; }
    else                      { W = wv; bias = bv; out = g_v; }

    __shared__ float As[8][128];   // As[k][m] (A transposed)
    __shared__ float Bs[8][128];   // Bs[k][n]

    const int tid  = threadIdx.x;
    const int row0 = blockIdx.x * 128;
    const int col0 = blockIdx.y * 128;

    const int ar  = tid >> 1,  ak4 = (tid & 1) * 4;   // A tile load coords
    const int bkr = tid >> 5,  bc4 = (tid & 31) * 4;  // B tile load coords
    const int ty  = tid >> 4,  tx  = tid & 15;
    const int r0  = ty * 8,    c0  = tx * 8;

    float acc[8][8];
#pragma unroll
    for (int i = 0; i < 8; i++)
#pragma unroll
        for (int j = 0; j < 8; j++) acc[i][j] = 0.f;

    for (int k0 = 0; k0 < DM_; k0 += 8) {
        float4 av  = *(const float4*)&x[(size_t)(row0 + ar) * DM_ + k0 + ak4];
        float4 bv4 = *(const float4*)&W[(size_t)(k0 + bkr) * NC + col0 + bc4];
        __syncthreads();
        As[ak4 + 0][ar] = av.x;
        As[ak4 + 1][ar] = av.y;
        As[ak4 + 2][ar] = av.z;
        As[ak4 + 3][ar] = av.w;
        *(float4*)&Bs[bkr][bc4] = bv4;
        __syncthreads();
#pragma unroll
        for (int kk = 0; kk < 8; kk++) {
            float a[8], bb[8];
            *(float4*)&a[0]  = *(const float4*)&As[kk][r0];
            *(float4*)&a[4]  = *(const float4*)&As[kk][r0 + 4];
            *(float4*)&bb[0] = *(const float4*)&Bs[kk][c0];
            *(float4*)&bb[4] = *(const float4*)&Bs[kk][c0 + 4];
#pragma unroll
            for (int i = 0; i < 8; i++)
#pragma unroll
                for (int j = 0; j < 8; j++)
                    acc[i][j] += a[i] * bb[j];
        }
    }

    float bj[8];
#pragma unroll
    for (int j = 0; j < 8; j++) bj[j] = bias[col0 + c0 + j];
#pragma unroll
    for (int i = 0; i < 8; i++) {
        float* orow = out + (size_t)(row0 + r0 + i) * NC + col0 + c0;
        float4 o0, o1;
        o0.x = acc[i][0] + bj[0]; o0.y = acc[i][1] + bj[1];
        o0.z = acc[i][2] + bj[2]; o0.w = acc[i][3] + bj[3];
        o1.x = acc[i][4] + bj[4]; o1.y = acc[i][5] + bj[5];
        o1.z = acc[i][6] + bj[6]; o1.w = acc[i][7] + bj[7];
        *(float4*)&orow[0] = o0;
        *(float4*)&orow[4] = o1;
    }
}

// ---------------------------------------------------------------------------
// Kernel 2: BigBird block-sparse attention. grid = (64, H, B), 256 threads.
// One CTA handles one 64-row q block; flash-streams over its key-block list
// (multiset exactly as the reference builds it, duplicates included).
// Shared: Qt[d][r] (scaled), KP = K (transposed) then P (xor-swizzled), V[c][d].
// ---------------------------------------------------------------------------
__global__ __launch_bounds__(256) void bigbird_attn(
    const int* __restrict__ rand_attn, float* __restrict__ out)
{
    __shared__ float Qt[64 * 64];
    __shared__ float KP[64 * 64];
    __shared__ float Vs[64 * 64];

    const int tid = threadIdx.x;
    const int b = blockIdx.z, h = blockIdx.y;
    const int qo = blockIdx.x;
    // Long blocks (0, 63: full attention, 64 tiles) scheduled first.
    const int qb = (qo == 0) ? 0 : (qo == 1) ? (NB_ - 1) : (qo - 1);

    int nblk;
    if (qb == 0 || qb == NB_ - 1)      nblk = NB_;
    else if (qb == 1 || qb == NB_ - 2) nblk = 7;
    else                               nblk = 8;

    int rbase = 0;
    if (qb >= 1 && qb <= NB_ - 2) rbase = (h * (NB_ - 2) + (qb - 1)) * R_;

    const size_t bh_off = ((size_t)b * S_) * NC + (size_t)h * D_;
    const float* qbase = g_q + bh_off + (size_t)qb * BS_ * NC;

    // Load Q transposed into shared, pre-scaled by 1/sqrt(D).
    const float scale = 0.125f;
    for (int idx = tid; idx < 1024; idx += 256) {
        int d4 = idx >> 6, r = idx & 63;
        float4 v = *(const float4*)&qbase[(size_t)r * NC + d4 * 4];
        Qt[(d4 * 4 + 0) * 64 + r] = v.x * scale;
        Qt[(d4 * 4 + 1) * 64 + r] = v.y * scale;
        Qt[(d4 * 4 + 2) * 64 + r] = v.z * scale;
        Qt[(d4 * 4 + 3) * 64 + r] = v.w * scale;
    }

    const int ty = tid >> 4, tx = tid & 15;
    const int r0 = ty * 4, c0 = tx * 4;

    float m_i[4], l_i[4], accv[4][4];
#pragma unroll
    for (int i = 0; i < 4; i++) {
        m_i[i] = -INFINITY; l_i[i] = 0.f;
#pragma unroll
        for (int j = 0; j < 4; j++) accv[i][j] = 0.f;
    }

    for (int t = 0; t < nblk; t++) {
        int kb;
        if (qb == 0 || qb == NB_ - 1) {
            kb = t;
        } else if (qb == 1) {
            kb = (t == 0) ? 0 : (t == 1) ? 1 : (t == 2) ? 2 :
                 (t == 3) ? (NB_ - 1) : rand_attn[rbase + t - 4];
        } else if (qb == NB_ - 2) {
            kb = (t == 0) ? 0 : (t == 1) ? (NB_ - 3) : (t == 2) ? (NB_ - 2) :
                 (t == 3) ? (NB_ - 1) : rand_attn[rbase + t - 4];
        } else {
            kb = (t == 0) ? 0 : (t == 1) ? (qb - 1) : (t == 2) ? qb :
                 (t == 3) ? (qb + 1) : (t == 4) ? (NB_ - 1)
                          : rand_attn[rbase + t - 5];
        }

        const float* kbase = g_k + bh_off + (size_t)kb * BS_ * NC;
        const float* vbase = g_v + bh_off + (size_t)kb * BS_ * NC;

        __syncthreads();   // previous tile's P/V reads complete
        // K transposed: KP[d][c]  (lanes vary over c -> conflict-free writes)
        for (int idx = tid; idx < 1024; idx += 256) {
            int d4 = idx >> 6, c = idx & 63;
            float4 v = *(const float4*)&kbase[(size_t)c * NC + d4 * 4];
            KP[(d4 * 4 + 0) * 64 + c] = v.x;
            KP[(d4 * 4 + 1) * 64 + c] = v.y;
            KP[(d4 * 4 + 2) * 64 + c] = v.z;
            KP[(d4 * 4 + 3) * 64 + c] = v.w;
        }
        // V row-major: Vs[c][d] (coalesced global, float4 shared writes)
        for (int idx = tid; idx < 1024; idx += 256) {
            int c = idx >> 4, d4 = idx & 15;
            float4 v = *(const float4*)&vbase[(size_t)c * NC + d4 * 4];
            *(float4*)&Vs[c * 64 + d4 * 4] = v;
        }
        __syncthreads();

        // S = (Q*scale) @ K^T : each thread 4x4 of the 64x64 score tile
        float s[4][4];
#pragma unroll
        for (int i = 0; i < 4; i++)
#pragma unroll
            for (int j = 0; j < 4; j++) s[i][j] = 0.f;
#pragma unroll 16
        for (int d = 0; d < 64; d++) {
            float qv[4], kv[4];
#pragma unroll
            for (int i = 0; i < 4; i++) qv[i] = Qt[d * 64 + r0 + i];
#pragma unroll
            for (int j = 0; j < 4; j++) kv[j] = KP[d * 64 + c0 + j];
#pragma unroll
            for (int i = 0; i < 4; i++)
#pragma unroll
                for (int j = 0; j < 4; j++)
                    s[i][j] += qv[i] * kv[j];
        }

        // Online softmax update (row stats redundant+consistent across the
        // 16 lanes covering each row; butterfly reductions are deterministic).
#pragma unroll
        for (int i = 0; i < 4; i++) {
            float mx = fmaxf(fmaxf(s[i][0], s[i][1]), fmaxf(s[i][2], s[i][3]));
#pragma unroll
            for (int off = 8; off >= 1; off >>= 1)
                mx = fmaxf(mx, __shfl_xor_sync(0xffffffffu, mx, off));
            float mnew  = fmaxf(m_i[i], mx);
            float alpha = __expf(m_i[i] - mnew);   // first tile: exp(-inf)=0
            float rs = 0.f;
#pragma unroll
            for (int j = 0; j < 4; j++) {
                s[i][j] = __expf(s[i][j] - mnew);
                rs += s[i][j];
            }
#pragma unroll
            for (int off = 8; off >= 1; off >>= 1)
                rs += __shfl_xor_sync(0xffffffffu, rs, off);
            l_i[i] = l_i[i] * alpha + rs;
            m_i[i] = mnew;
#pragma unroll
            for (int j = 0; j < 4; j++) accv[i][j] *= alpha;
        }

        __syncthreads();   // all K reads done before P overwrites the buffer
        // Store P xor-swizzled: phys = r*64 + (c ^ r)  (bijective per row)
#pragma unroll
        for (int i = 0; i < 4; i++)
#pragma unroll
            for (int j = 0; j < 4; j++)
                KP[(r0 + i) * 64 + ((c0 + j) ^ (r0 + i))] = s[i][j];
        __syncthreads();

        // O += P @ V
#pragma unroll 8
        for (int c = 0; c < 64; c++) {
            float pv[4], vv[4];
#pragma unroll
            for (int i = 0; i < 4; i++)
                pv[i] = KP[(r0 + i) * 64 + (c ^ (r0 + i))];
#pragma unroll
            for (int j = 0; j < 4; j++)
                vv[j] = Vs[c * 64 + c0 + j];
#pragma unroll
            for (int i = 0; i < 4; i++)
#pragma unroll
                for (int j = 0; j < 4; j++)
                    accv[i][j] += pv[i] * vv[j];
        }
    }

    // Normalize and write: out[(b*S + qb*64 + r)*512 + h*64 + d]
    float* obase = out + bh_off + (size_t)qb * BS_ * NC;
#pragma unroll
    for (int i = 0; i < 4; i++) {
        float inv = 1.f / l_i[i];
#pragma unroll
        for (int j = 0; j < 4; j++)
            obase[(size_t)(r0 + i) * NC + c0 + j] = accv[i][j] * inv;
    }
}

// ---------------------------------------------------------------------------
extern "C" void kernel_launch(void* const* d_in, const int* in_sizes, int n_in,
                              void* d_out, int out_size)
{
    const float* x  = (const float*)d_in[0];
    const float* wq = (const float*)d_in[1];
    const float* bq = (const float*)d_in[2];
    const float* wk = (const float*)d_in[3];
    const float* bk = (const float*)d_in[4];
    const float* wv = (const float*)d_in[5];
    const float* bv = (const float*)d_in[6];
    const int* rand_attn = (const int*)d_in[7];
    float* out = (float*)d_out;

    dim3 g1(MROWS / 128, NC / 128, 3);
    qkv_gemm<<<g1, 256>>>(x, wq, bq, wk, bk, wv, bv);

    dim3 g2(NB_, H_, B_);
    bigbird_attn<<<g2, 256>>>(rand_attn, out);
}

// round 2
// speedup vs baseline: 1.5648x; 1.5648x over previous
#include <cuda_runtime.h>
#include <math.h>

#define B_ 2
#define S_ 4096
#define DM_ 512
#define H_ 8
#define D_ 64
#define BS_ 64
#define NB_ 64
#define R_ 3
#define MROWS (B_*S_)   /* 8192 */
#define NC (H_*D_)      /* 512  */
#define NCHUNK 8        /* long-block split factor */

// Scratch for projected Q/K/V in [B*S, H*D] layout (16 MB each).
__device__ float g_q[MROWS * NC];
__device__ float g_k[MROWS * NC];
__device__ float g_v[MROWS * NC];

// Split-softmax partials for the two full-attention blocks (0 and 63).
// Layout: [li(2)][b][h][chunk(8)][row(64)][d(64)]
__device__ float g_pacc[2 * B_ * H_ * NCHUNK * 64 * 64];
__device__ float g_pm[2 * B_ * H_ * NCHUNK * 64];
__device__ float g_pl[2 * B_ * H_ * NCHUNK * 64];

// ---------------------------------------------------------------------------
// Kernel 1: fused QKV projection. grid = (M/128, 512/128, 3), 256 threads.
// ---------------------------------------------------------------------------
__global__ __launch_bounds__(256) void qkv_gemm(
    const float* __restrict__ x,
    const float* __restrict__ wq, const float* __restrict__ bq,
    const float* __restrict__ wk, const float* __restrict__ bk,
    const float* __restrict__ wv, const float* __restrict__ bv)
{
    const float* W; const float* bias; float* out;
    if (blockIdx.z == 0)      { W = wq; bias = bq; out = g_q; }
    else if (blockIdx.z == 1) { W = wk; bias = bk; out = g_k; }
    else                      { W = wv; bias = bv; out = g_v; }

    __shared__ float As[8][128];
    __shared__ float Bs[8][128];

    const int tid  = threadIdx.x;
    const int row0 = blockIdx.x * 128;
    const int col0 = blockIdx.y * 128;

    const int ar  = tid >> 1,  ak4 = (tid & 1) * 4;
    const int bkr = tid >> 5,  bc4 = (tid & 31) * 4;
    const int ty  = tid >> 4,  tx  = tid & 15;
    const int r0  = ty * 8,    c0  = tx * 8;

    float acc[8][8];
#pragma unroll
    for (int i = 0; i < 8; i++)
#pragma unroll
        for (int j = 0; j < 8; j++) acc[i][j] = 0.f;

    for (int k0 = 0; k0 < DM_; k0 += 8) {
        float4 av  = *(const float4*)&x[(size_t)(row0 + ar) * DM_ + k0 + ak4];
        float4 bv4 = *(const float4*)&W[(size_t)(k0 + bkr) * NC + col0 + bc4];
        __syncthreads();
        As[ak4 + 0][ar] = av.x;
        As[ak4 + 1][ar] = av.y;
        As[ak4 + 2][ar] = av.z;
        As[ak4 + 3][ar] = av.w;
        *(float4*)&Bs[bkr][bc4] = bv4;
        __syncthreads();
#pragma unroll
        for (int kk = 0; kk < 8; kk++) {
            float a[8], bb[8];
            *(float4*)&a[0]  = *(const float4*)&As[kk][r0];
            *(float4*)&a[4]  = *(const float4*)&As[kk][r0 + 4];
            *(float4*)&bb[0] = *(const float4*)&Bs[kk][c0];
            *(float4*)&bb[4] = *(const float4*)&Bs[kk][c0 + 4];
#pragma unroll
            for (int i = 0; i < 8; i++)
#pragma unroll
                for (int j = 0; j < 8; j++)
                    acc[i][j] += a[i] * bb[j];
        }
    }

    float bj[8];
#pragma unroll
    for (int j = 0; j < 8; j++) bj[j] = bias[col0 + c0 + j];
#pragma unroll
    for (int i = 0; i < 8; i++) {
        float* orow = out + (size_t)(row0 + r0 + i) * NC + col0 + c0;
        float4 o0, o1;
        o0.x = acc[i][0] + bj[0]; o0.y = acc[i][1] + bj[1];
        o0.z = acc[i][2] + bj[2]; o0.w = acc[i][3] + bj[3];
        o1.x = acc[i][4] + bj[4]; o1.y = acc[i][5] + bj[5];
        o1.z = acc[i][6] + bj[6]; o1.w = acc[i][7] + bj[7];
        *(float4*)&orow[0] = o0;
        *(float4*)&orow[4] = o1;
    }
}

// ---------------------------------------------------------------------------
// Kernel 2: BigBird block-sparse attention, load-balanced.
// grid = (78, H, B), 256 threads.
//   blockIdx.x in [0,16):  long-block chunks. li = x>>3 (block 0 / 63),
//                          chunk = x&7, key tiles kb = chunk*8 + t, t<8.
//                          Writes unnormalized flash partials to scratch.
//   blockIdx.x in [16,78): qb = x-15 in [1,62], writes output directly.
// Shared: Qt[d][r] scaled, KP = K^T then P^T (xor-swizzled), Vs[c][d].
// ---------------------------------------------------------------------------
__global__ __launch_bounds__(256) void bigbird_attn(
    const int* __restrict__ rand_attn, float* __restrict__ out)
{
    __shared__ float Qt[64 * 64];
    __shared__ float KP[64 * 64];
    __shared__ float Vs[64 * 64];

    const int tid = threadIdx.x;
    const int b = blockIdx.z, h = blockIdx.y;
    const int x = blockIdx.x;

    const bool isLong = (x < 2 * NCHUNK);
    int li = 0, chunk = 0, qb, nblk;
    if (isLong) {
        li = x >> 3; chunk = x & 7;
        qb = li ? (NB_ - 1) : 0;
        nblk = 8;
    } else {
        qb = x - 15;                       // 1..62
        nblk = (qb == 1 || qb == NB_ - 2) ? 7 : 8;
    }

    int rbase = 0;
    if (!isLong) rbase = (h * (NB_ - 2) + (qb - 1)) * R_;

    const size_t bh_off = ((size_t)b * S_) * NC + (size_t)h * D_;
    const float* qbase = g_q + bh_off + (size_t)qb * BS_ * NC;

    // Load Q transposed into shared, pre-scaled by 1/sqrt(D).
    const float scale = 0.125f;
    for (int idx = tid; idx < 1024; idx += 256) {
        int d4 = idx >> 6, r = idx & 63;
        float4 v = *(const float4*)&qbase[(size_t)r * NC + d4 * 4];
        Qt[(d4 * 4 + 0) * 64 + r] = v.x * scale;
        Qt[(d4 * 4 + 1) * 64 + r] = v.y * scale;
        Qt[(d4 * 4 + 2) * 64 + r] = v.z * scale;
        Qt[(d4 * 4 + 3) * 64 + r] = v.w * scale;
    }

    const int ty = tid >> 4, tx = tid & 15;
    const int r0 = ty * 4, c0 = tx * 4;

    float m_i[4], l_i[4], accv[4][4];
#pragma unroll
    for (int i = 0; i < 4; i++) {
        m_i[i] = -INFINITY; l_i[i] = 0.f;
#pragma unroll
        for (int j = 0; j < 4; j++) accv[i][j] = 0.f;
    }

    for (int t = 0; t < nblk; t++) {
        int kb;
        if (isLong) {
            kb = chunk * 8 + t;
        } else if (qb == 1) {
            kb = (t == 0) ? 0 : (t == 1) ? 1 : (t == 2) ? 2 :
                 (t == 3) ? (NB_ - 1) : rand_attn[rbase + t - 4];
        } else if (qb == NB_ - 2) {
            kb = (t == 0) ? 0 : (t == 1) ? (NB_ - 3) : (t == 2) ? (NB_ - 2) :
                 (t == 3) ? (NB_ - 1) : rand_attn[rbase + t - 4];
        } else {
            kb = (t == 0) ? 0 : (t == 1) ? (qb - 1) : (t == 2) ? qb :
                 (t == 3) ? (qb + 1) : (t == 4) ? (NB_ - 1)
                          : rand_attn[rbase + t - 5];
        }

        const float* kbase = g_k + bh_off + (size_t)kb * BS_ * NC;
        const float* vbase = g_v + bh_off + (size_t)kb * BS_ * NC;

        __syncthreads();   // previous tile's P^T/V reads complete
        // K transposed: KP[d][c]
        for (int idx = tid; idx < 1024; idx += 256) {
            int d4 = idx >> 6, c = idx & 63;
            float4 v = *(const float4*)&kbase[(size_t)c * NC + d4 * 4];
            KP[(d4 * 4 + 0) * 64 + c] = v.x;
            KP[(d4 * 4 + 1) * 64 + c] = v.y;
            KP[(d4 * 4 + 2) * 64 + c] = v.z;
            KP[(d4 * 4 + 3) * 64 + c] = v.w;
        }
        // V row-major: Vs[c][d]
        for (int idx = tid; idx < 1024; idx += 256) {
            int c = idx >> 4, d4 = idx & 15;
            float4 v = *(const float4*)&vbase[(size_t)c * NC + d4 * 4];
            *(float4*)&Vs[c * 64 + d4 * 4] = v;
        }
        __syncthreads();

        // S = (Q*scale) @ K^T : 4x4 per thread of the 64x64 tile
        float s[4][4];
#pragma unroll
        for (int i = 0; i < 4; i++)
#pragma unroll
            for (int j = 0; j < 4; j++) s[i][j] = 0.f;
#pragma unroll 16
        for (int d = 0; d < 64; d++) {
            float qv[4], kv[4];
            *(float4*)qv = *(const float4*)&Qt[d * 64 + r0];
            *(float4*)kv = *(const float4*)&KP[d * 64 + c0];
#pragma unroll
            for (int i = 0; i < 4; i++)
#pragma unroll
                for (int j = 0; j < 4; j++)
                    s[i][j] += qv[i] * kv[j];
        }

        // Online softmax (row stats replicated across the 16 lanes per row).
#pragma unroll
        for (int i = 0; i < 4; i++) {
            float mx = fmaxf(fmaxf(s[i][0], s[i][1]), fmaxf(s[i][2], s[i][3]));
#pragma unroll
            for (int off = 8; off >= 1; off >>= 1)
                mx = fmaxf(mx, __shfl_xor_sync(0xffffffffu, mx, off));
            float mnew  = fmaxf(m_i[i], mx);
            float alpha = __expf(m_i[i] - mnew);
            float rs = 0.f;
#pragma unroll
            for (int j = 0; j < 4; j++) {
                s[i][j] = __expf(s[i][j] - mnew);
                rs += s[i][j];
            }
#pragma unroll
            for (int off = 8; off >= 1; off >>= 1)
                rs += __shfl_xor_sync(0xffffffffu, rs, off);
            l_i[i] = l_i[i] * alpha + rs;
            m_i[i] = mnew;
#pragma unroll
            for (int j = 0; j < 4; j++) accv[i][j] *= alpha;
        }

        __syncthreads();   // all K reads done before P^T overwrites buffer
        // Store P TRANSPOSED, xor-swizzled per column:
        //   phys(c, r) = c*64 + (r0 ^ ((c&15)<<2)) + (r-r0), float4 over rows
#pragma unroll
        for (int j = 0; j < 4; j++) {
            int c = c0 + j;
            float4 pv4;
            pv4.x = s[0][j]; pv4.y = s[1][j]; pv4.z = s[2][j]; pv4.w = s[3][j];
            *(float4*)&KP[c * 64 + (r0 ^ ((c & 15) << 2))] = pv4;
        }
        __syncthreads();

        // O += P @ V : per c, one broadcast LDS.128 (P^T) + one LDS.128 (V)
#pragma unroll 8
        for (int c = 0; c < 64; c++) {
            float4 p4 = *(const float4*)&KP[c * 64 + (r0 ^ ((c & 15) << 2))];
            float4 v4 = *(const float4*)&Vs[c * 64 + c0];
            float pv[4] = {p4.x, p4.y, p4.z, p4.w};
            float vv[4] = {v4.x, v4.y, v4.z, v4.w};
#pragma unroll
            for (int i = 0; i < 4; i++)
#pragma unroll
                for (int j = 0; j < 4; j++)
                    accv[i][j] += pv[i] * vv[j];
        }
    }

    if (!isLong) {
        // Normalize and write final output rows.
        float* obase = out + bh_off + (size_t)qb * BS_ * NC;
#pragma unroll
        for (int i = 0; i < 4; i++) {
            float inv = 1.f / l_i[i];
            float4 o;
            o.x = accv[i][0] * inv; o.y = accv[i][1] * inv;
            o.z = accv[i][2] * inv; o.w = accv[i][3] * inv;
            *(float4*)&obase[(size_t)(r0 + i) * NC + c0] = o;
        }
    } else {
        // Write unnormalized flash partials for the combine kernel.
        const int bh8 = ((li * B_ + b) * H_ + h) * NCHUNK + chunk;
        if (tx == 0) {
#pragma unroll
            for (int i = 0; i < 4; i++) {
                g_pm[bh8 * 64 + r0 + i] = m_i[i];
                g_pl[bh8 * 64 + r0 + i] = l_i[i];
            }
        }
#pragma unroll
        for (int i = 0; i < 4; i++) {
            float4 a;
            a.x = accv[i][0]; a.y = accv[i][1];
            a.z = accv[i][2]; a.w = accv[i][3];
            *(float4*)&g_pacc[(size_t)(bh8 * 64 + r0 + i) * 64 + c0] = a;
        }
    }
}

// ---------------------------------------------------------------------------
// Kernel 3: combine split-softmax partials for blocks 0 and 63.
// grid = (2, H, B), 256 threads. thread -> (row = t>>2, 16 d-values).
// ---------------------------------------------------------------------------
__global__ __launch_bounds__(256) void bb_combine(float* __restrict__ out)
{
    const int li = blockIdx.x, h = blockIdx.y, b = blockIdx.z;
    const int t = threadIdx.x;
    const int r = t >> 2;
    const int d0 = (t & 3) * 16;

    const int bhc0 = ((li * B_ + b) * H_ + h) * NCHUNK;

    float m[NCHUNK], w[NCHUNK];
    float M = -INFINITY;
#pragma unroll
    for (int c = 0; c < NCHUNK; c++) {
        m[c] = g_pm[(bhc0 + c) * 64 + r];
        M = fmaxf(M, m[c]);
    }
    float L = 0.f;
#pragma unroll
    for (int c = 0; c < NCHUNK; c++) {
        w[c] = __expf(m[c] - M);
        L += g_pl[(bhc0 + c) * 64 + r] * w[c];
    }
    const float inv = 1.f / L;

    const int qb = li ? (NB_ - 1) : 0;
    float* obase = out + ((size_t)b * S_ + (size_t)qb * BS_ + r) * NC
                       + (size_t)h * D_ + d0;

#pragma unroll
    for (int dd = 0; dd < 16; dd += 4) {
        float4 o; o.x = o.y = o.z = o.w = 0.f;
#pragma unroll
        for (int c = 0; c < NCHUNK; c++) {
            const float4 a = *(const float4*)
                &g_pacc[(size_t)((bhc0 + c) * 64 + r) * 64 + d0 + dd];
            o.x += a.x * w[c]; o.y += a.y * w[c];
            o.z += a.z * w[c]; o.w += a.w * w[c];
        }
        o.x *= inv; o.y *= inv; o.z *= inv; o.w *= inv;
        *(float4*)&obase[dd] = o;
    }
}

// ---------------------------------------------------------------------------
extern "C" void kernel_launch(void* const* d_in, const int* in_sizes, int n_in,
                              void* d_out, int out_size)
{
    const float* x  = (const float*)d_in[0];
    const float* wq = (const float*)d_in[1];
    const float* bq = (const float*)d_in[2];
    const float* wk = (const float*)d_in[3];
    const float* bk = (const float*)d_in[4];
    const float* wv = (const float*)d_in[5];
    const float* bv = (const float*)d_in[6];
    const int* rand_attn = (const int*)d_in[7];
    float* out = (float*)d_out;

    dim3 g1(MROWS / 128, NC / 128, 3);
    qkv_gemm<<<g1, 256>>>(x, wq, bq, wk, bk, wv, bv);

    dim3 g2(2 * NCHUNK + (NB_ - 2), H_, B_);   // 78 x 8 x 2 = 1248 CTAs
    bigbird_attn<<<g2, 256>>>(rand_attn, out);

    dim3 g3(2, H_, B_);
    bb_combine<<<g3, 256>>>(out);
}

// round 4
// speedup vs baseline: 2.3270x; 1.4871x over previous
#include <cuda_runtime.h>
#include <cuda_bf16.h>
#include <math.h>
#include <stdint.h>

#define B_ 2
#define S_ 4096
#define DM_ 512
#define H_ 8
#define D_ 64
#define BS_ 64
#define NB_ 64
#define R_ 3
#define MROWS (B_*S_)   /* 8192 */
#define NC (H_*D_)      /* 512  */
#define NCHUNK 8        /* long-block split factor */

// fp32 projected Q/K/V in [B*S, H*D] layout (16 MB each).
__device__ float g_q[MROWS * NC];
__device__ float g_k[MROWS * NC];
__device__ float g_v[MROWS * NC];

// bf16 hi/lo decomposition of x (row-major [M, K]).
__device__ __nv_bfloat16 g_xhi[MROWS * DM_];
__device__ __nv_bfloat16 g_xlo[MROWS * DM_];
// bf16 hi/lo of transposed weights: [z][n][k].
__device__ __nv_bfloat16 g_wthi[3 * DM_ * NC];
__device__ __nv_bfloat16 g_wtlo[3 * DM_ * NC];

// Split-softmax partials for the two full-attention blocks (0 and 63).
__device__ float g_pacc[2 * B_ * H_ * NCHUNK * 64 * 64];
__device__ float g_pm[2 * B_ * H_ * NCHUNK * 64];
__device__ float g_pl[2 * B_ * H_ * NCHUNK * 64];

// ---------------------------------------------------------------------------
// Portable PTX helpers (compute_80+; no tcgen05 — base target is sm_103).
// ---------------------------------------------------------------------------
__device__ __forceinline__ uint32_t smem_u32(const void* p) {
    uint32_t a;
    asm("{ .reg .u64 t; cvta.to.shared.u64 t, %1; cvt.u32.u64 %0, t; }"
        : "=r"(a) : "l"(p));
    return a;
}
#define CP_ASYNC16(saddr, gptr) \
    asm volatile("cp.async.cg.shared.global [%0], [%1], 16;" \
                 :: "r"(saddr), "l"(gptr) : "memory")
#define CP_COMMIT() asm volatile("cp.async.commit_group;" ::: "memory")
#define CP_WAIT0()  asm volatile("cp.async.wait_group 0;" ::: "memory")

#define LDSM_X4(r0, r1, r2, r3, addr) \
    asm volatile("ldmatrix.sync.aligned.m8n8.x4.shared.b16 {%0,%1,%2,%3}, [%4];" \
                 : "=r"(r0), "=r"(r1), "=r"(r2), "=r"(r3) : "r"(addr))

#define MMA16816(d, a, b0, b1) \
    asm volatile("mma.sync.aligned.m16n8k16.row.col.f32.bf16.bf16.f32 " \
                 "{%0,%1,%2,%3}, {%4,%5,%6,%7}, {%8,%9}, {%0,%1,%2,%3};" \
                 : "+f"((d)[0]), "+f"((d)[1]), "+f"((d)[2]), "+f"((d)[3]) \
                 : "r"((a)[0]), "r"((a)[1]), "r"((a)[2]), "r"((a)[3]), \
                   "r"(b0), "r"(b1))

#define SW128(o) ((o) ^ (((o) >> 3) & 0x70))

// ---------------------------------------------------------------------------
// Prep 1: split x into bf16 hi/lo. grid 4096, 256 thr, 4 elems/thread.
// ---------------------------------------------------------------------------
__global__ __launch_bounds__(256) void xsplit(const float* __restrict__ x)
{
    size_t i4 = ((size_t)blockIdx.x * 256 + threadIdx.x) * 4;
    float4 v = *(const float4*)(x + i4);
    union { __nv_bfloat16 b[4]; uint2 u; } Hu, Lu;
    float vv[4] = {v.x, v.y, v.z, v.w};
#pragma unroll
    for (int k = 0; k < 4; k++) {
        __nv_bfloat16 h = __float2bfloat16(vv[k]);
        Hu.b[k] = h;
        Lu.b[k] = __float2bfloat16(vv[k] - __bfloat162float(h));
    }
    *(uint2*)(g_xhi + i4) = Hu.u;
    *(uint2*)(g_xlo + i4) = Lu.u;
}

// ---------------------------------------------------------------------------
// Prep 2: transpose + split weights. grid (8, 8, 3), 256 thr, 64x64 tiles.
// ---------------------------------------------------------------------------
__global__ __launch_bounds__(256) void wsplit(
    const float* __restrict__ wq, const float* __restrict__ wk,
    const float* __restrict__ wv)
{
    const int z = blockIdx.z;
    const float* w = (z == 0) ? wq : (z == 1) ? wk : wv;
    __nv_bfloat16* oh = g_wthi + (size_t)z * DM_ * NC;
    __nv_bfloat16* ol = g_wtlo + (size_t)z * DM_ * NC;
    __shared__ float t[64][65];
    const int n0 = blockIdx.x * 64, k0 = blockIdx.y * 64;
    const int tx = threadIdx.x & 63, ty = threadIdx.x >> 6;
#pragma unroll
    for (int i = 0; i < 16; i++) {
        int r = ty + i * 4;
        t[r][tx] = w[(size_t)(k0 + r) * NC + n0 + tx];
    }
    __syncthreads();
#pragma unroll
    for (int i = 0; i < 16; i++) {
        int r = ty + i * 4;                // n index
        float v = t[tx][r];
        __nv_bfloat16 h = __float2bfloat16(v);
        oh[(size_t)(n0 + r) * DM_ + k0 + tx] = h;
        ol[(size_t)(n0 + r) * DM_ + k0 + tx] =
            __float2bfloat16(v - __bfloat162float(h));
    }
}

// ---------------------------------------------------------------------------
// QKV projection via mma.sync bf16, 3-term hi/lo decomposition.
// grid (4, 64, 3), 256 thr (8 warps, 2x4 grid; warp tile 64x32).
// K=512 in 8 chunks of 64; cp.async double-buffered SMEM tiles.
// SMEM: 1024B header + 2 bufs x (Ahi, Alo, Bhi, Blo: 16KB each) = 132096 B.
// ---------------------------------------------------------------------------
#define QKV_SMEM (1024 + 8 * 16384)

__global__ __launch_bounds__(256, 1) void qkv_mma(
    const float* __restrict__ bq, const float* __restrict__ bk,
    const float* __restrict__ bv)
{
    extern __shared__ __align__(1024) char smem[];
    const int tid = threadIdx.x;
    const int z = blockIdx.z;
    const int col0 = blockIdx.x * 128;   // N tile
    const int row0 = blockIdx.y * 128;   // M tile

    const float* bias = (z == 0) ? bq : (z == 1) ? bk : bv;
    float* outp = (z == 0) ? g_q : (z == 1) ? g_k : g_v;
    const __nv_bfloat16* Bhg = g_wthi + (size_t)z * DM_ * NC;
    const __nv_bfloat16* Blg = g_wtlo + (size_t)z * DM_ * NC;

    const uint32_t sb = smem_u32(smem) + 1024;

    const int lane = tid & 31, w = tid >> 5;
    const int wm = (w & 1) * 64;     // warp M base in tile
    const int wn = (w >> 1) * 32;    // warp N base in tile

    // Per-thread load coords (16 x cp.async of 16B per chunk).
    const int lr = tid >> 1;              // 0..127 row
    // each thread covers rows lr, columns: 2 groups of 16B? -> use 4 iters:
    //   lin = tid + i*256: r = lin>>3, c8 = lin&7  (8 bf16 = 16B groups)

    float acc[4][4][4];
#pragma unroll
    for (int mt = 0; mt < 4; mt++)
#pragma unroll
        for (int nt = 0; nt < 4; nt++)
#pragma unroll
            for (int e = 0; e < 4; e++) acc[mt][nt][e] = 0.f;

    // ---- chunk loader (cp.async) ----
    auto load_chunk = [&](int ch, int buf) {
        const uint32_t tb = sb + buf * 65536;
#pragma unroll
        for (int i = 0; i < 4; i++) {
            int lin = tid + i * 256;
            int r = lin >> 3, c8 = lin & 7;
            size_t ga = (size_t)(row0 + r) * DM_ + ch * 64 + c8 * 8;
            size_t gb = (size_t)(col0 + r) * DM_ + ch * 64 + c8 * 8;
            uint32_t so = SW128((uint32_t)(r * 128 + c8 * 16));
            CP_ASYNC16(tb + so,         g_xhi + ga);
            CP_ASYNC16(tb + 16384 + so, g_xlo + ga);
            CP_ASYNC16(tb + 32768 + so, Bhg + gb);
            CP_ASYNC16(tb + 49152 + so, Blg + gb);
        }
    };

    load_chunk(0, 0);
    CP_COMMIT();
    CP_WAIT0();
    __syncthreads();

    for (int ch = 0; ch < 8; ch++) {
        const int buf = ch & 1;
        if (ch < 7) { load_chunk(ch + 1, buf ^ 1); CP_COMMIT(); }

        const uint32_t tb = sb + buf * 65536;
        const uint32_t tAh = tb, tAl = tb + 16384;
        const uint32_t tBh = tb + 32768, tBl = tb + 49152;

#pragma unroll
        for (int ks = 0; ks < 4; ks++) {
            // A fragments (hi & lo): 4 m16 tiles each.
            uint32_t ah[4][4], al[4][4];
#pragma unroll
            for (int mt = 0; mt < 4; mt++) {
                int row = wm + mt * 16 + (lane & 15);
                uint32_t off = (uint32_t)(row * 128 + ks * 32 + (lane >> 4) * 16);
                uint32_t sw = SW128(off);
                LDSM_X4(ah[mt][0], ah[mt][1], ah[mt][2], ah[mt][3], tAh + sw);
                LDSM_X4(al[mt][0], al[mt][1], al[mt][2], al[mt][3], tAl + sw);
            }
            // B fragments (hi & lo): 2 x4 loads cover n16 x k16 (2 frags each).
            uint32_t bh[2][4], bl[2][4];
#pragma unroll
            for (int p = 0; p < 2; p++) {
                int nrow = wn + p * 16 + (lane & 7) + ((lane >> 4) << 3);
                uint32_t off = (uint32_t)(nrow * 128 + ks * 32 + ((lane >> 3) & 1) * 16);
                uint32_t sw = SW128(off);
                LDSM_X4(bh[p][0], bh[p][1], bh[p][2], bh[p][3], tBh + sw);
                LDSM_X4(bl[p][0], bl[p][1], bl[p][2], bl[p][3], tBl + sw);
            }
            // ldmatrix x4 register order for B block (lanes: n0-7/k0, n0-7/k8,
            // n8-15/k0, n8-15/k8) -> frag(n0-7)={r0,r1}, frag(n8-15)={r2,r3}.
#pragma unroll
            for (int mt = 0; mt < 4; mt++)
#pragma unroll
                for (int nt = 0; nt < 4; nt++) {
                    const int p = nt >> 1, s = (nt & 1) * 2;
                    MMA16816(acc[mt][nt], ah[mt], bh[p][s], bh[p][s + 1]);
                    MMA16816(acc[mt][nt], ah[mt], bl[p][s], bl[p][s + 1]);
                    MMA16816(acc[mt][nt], al[mt], bh[p][s], bh[p][s + 1]);
                }
        }
        CP_WAIT0();
        __syncthreads();
    }

    // Epilogue: direct stores + bias.  d0=C[q][i2] d1=C[q][i2+1]
    //                                  d2=C[q+8][i2] d3=C[q+8][i2+1]
    const int q = lane >> 2, iq = (lane & 3) * 2;
#pragma unroll
    for (int nt = 0; nt < 4; nt++) {
        const int gn = col0 + wn + nt * 8 + iq;
        const float b0 = bias[gn], b1 = bias[gn + 1];
#pragma unroll
        for (int mt = 0; mt < 4; mt++) {
            const int gm = row0 + wm + mt * 16 + q;
            float2 v0, v1;
            v0.x = acc[mt][nt][0] + b0; v0.y = acc[mt][nt][1] + b1;
            v1.x = acc[mt][nt][2] + b0; v1.y = acc[mt][nt][3] + b1;
            *(float2*)&outp[(size_t)gm * NC + gn]       = v0;
            *(float2*)&outp[(size_t)(gm + 8) * NC + gn] = v1;
        }
    }
}

// ---------------------------------------------------------------------------
// BigBird block-sparse attention (unchanged, passing, from round 2).
// ---------------------------------------------------------------------------
__global__ __launch_bounds__(256) void bigbird_attn(
    const int* __restrict__ rand_attn, float* __restrict__ out)
{
    __shared__ float Qt[64 * 64];
    __shared__ float KP[64 * 64];
    __shared__ float Vs[64 * 64];

    const int tid = threadIdx.x;
    const int b = blockIdx.z, h = blockIdx.y;
    const int x = blockIdx.x;

    const bool isLong = (x < 2 * NCHUNK);
    int li = 0, chunk = 0, qb, nblk;
    if (isLong) {
        li = x >> 3; chunk = x & 7;
        qb = li ? (NB_ - 1) : 0;
        nblk = 8;
    } else {
        qb = x - 15;
        nblk = (qb == 1 || qb == NB_ - 2) ? 7 : 8;
    }

    int rbase = 0;
    if (!isLong) rbase = (h * (NB_ - 2) + (qb - 1)) * R_;

    const size_t bh_off = ((size_t)b * S_) * NC + (size_t)h * D_;
    const float* qbase = g_q + bh_off + (size_t)qb * BS_ * NC;

    const float scale = 0.125f;
    for (int idx = tid; idx < 1024; idx += 256) {
        int d4 = idx >> 6, r = idx & 63;
        float4 v = *(const float4*)&qbase[(size_t)r * NC + d4 * 4];
        Qt[(d4 * 4 + 0) * 64 + r] = v.x * scale;
        Qt[(d4 * 4 + 1) * 64 + r] = v.y * scale;
        Qt[(d4 * 4 + 2) * 64 + r] = v.z * scale;
        Qt[(d4 * 4 + 3) * 64 + r] = v.w * scale;
    }

    const int ty = tid >> 4, tx = tid & 15;
    const int r0 = ty * 4, c0 = tx * 4;

    float m_i[4], l_i[4], accv[4][4];
#pragma unroll
    for (int i = 0; i < 4; i++) {
        m_i[i] = -INFINITY; l_i[i] = 0.f;
#pragma unroll
        for (int j = 0; j < 4; j++) accv[i][j] = 0.f;
    }

    for (int t = 0; t < nblk; t++) {
        int kb;
        if (isLong) {
            kb = chunk * 8 + t;
        } else if (qb == 1) {
            kb = (t == 0) ? 0 : (t == 1) ? 1 : (t == 2) ? 2 :
                 (t == 3) ? (NB_ - 1) : rand_attn[rbase + t - 4];
        } else if (qb == NB_ - 2) {
            kb = (t == 0) ? 0 : (t == 1) ? (NB_ - 3) : (t == 2) ? (NB_ - 2) :
                 (t == 3) ? (NB_ - 1) : rand_attn[rbase + t - 4];
        } else {
            kb = (t == 0) ? 0 : (t == 1) ? (qb - 1) : (t == 2) ? qb :
                 (t == 3) ? (qb + 1) : (t == 4) ? (NB_ - 1)
                          : rand_attn[rbase + t - 5];
        }

        const float* kbase = g_k + bh_off + (size_t)kb * BS_ * NC;
        const float* vbase = g_v + bh_off + (size_t)kb * BS_ * NC;

        __syncthreads();
        for (int idx = tid; idx < 1024; idx += 256) {
            int d4 = idx >> 6, c = idx & 63;
            float4 v = *(const float4*)&kbase[(size_t)c * NC + d4 * 4];
            KP[(d4 * 4 + 0) * 64 + c] = v.x;
            KP[(d4 * 4 + 1) * 64 + c] = v.y;
            KP[(d4 * 4 + 2) * 64 + c] = v.z;
            KP[(d4 * 4 + 3) * 64 + c] = v.w;
        }
        for (int idx = tid; idx < 1024; idx += 256) {
            int c = idx >> 4, d4 = idx & 15;
            float4 v = *(const float4*)&vbase[(size_t)c * NC + d4 * 4];
            *(float4*)&Vs[c * 64 + d4 * 4] = v;
        }
        __syncthreads();

        float s[4][4];
#pragma unroll
        for (int i = 0; i < 4; i++)
#pragma unroll
            for (int j = 0; j < 4; j++) s[i][j] = 0.f;
#pragma unroll 16
        for (int d = 0; d < 64; d++) {
            float qv[4], kv[4];
            *(float4*)qv = *(const float4*)&Qt[d * 64 + r0];
            *(float4*)kv = *(const float4*)&KP[d * 64 + c0];
#pragma unroll
            for (int i = 0; i < 4; i++)
#pragma unroll
                for (int j = 0; j < 4; j++)
                    s[i][j] += qv[i] * kv[j];
        }

#pragma unroll
        for (int i = 0; i < 4; i++) {
            float mx = fmaxf(fmaxf(s[i][0], s[i][1]), fmaxf(s[i][2], s[i][3]));
#pragma unroll
            for (int off = 8; off >= 1; off >>= 1)
                mx = fmaxf(mx, __shfl_xor_sync(0xffffffffu, mx, off));
            float mnew  = fmaxf(m_i[i], mx);
            float alpha = __expf(m_i[i] - mnew);
            float rs = 0.f;
#pragma unroll
            for (int j = 0; j < 4; j++) {
                s[i][j] = __expf(s[i][j] - mnew);
                rs += s[i][j];
            }
#pragma unroll
            for (int off = 8; off >= 1; off >>= 1)
                rs += __shfl_xor_sync(0xffffffffu, rs, off);
            l_i[i] = l_i[i] * alpha + rs;
            m_i[i] = mnew;
#pragma unroll
            for (int j = 0; j < 4; j++) accv[i][j] *= alpha;
        }

        __syncthreads();
#pragma unroll
        for (int j = 0; j < 4; j++) {
            int c = c0 + j;
            float4 pv4;
            pv4.x = s[0][j]; pv4.y = s[1][j]; pv4.z = s[2][j]; pv4.w = s[3][j];
            *(float4*)&KP[c * 64 + (r0 ^ ((c & 15) << 2))] = pv4;
        }
        __syncthreads();

#pragma unroll 8
        for (int c = 0; c < 64; c++) {
            float4 p4 = *(const float4*)&KP[c * 64 + (r0 ^ ((c & 15) << 2))];
            float4 v4 = *(const float4*)&Vs[c * 64 + c0];
            float pv[4] = {p4.x, p4.y, p4.z, p4.w};
            float vv[4] = {v4.x, v4.y, v4.z, v4.w};
#pragma unroll
            for (int i = 0; i < 4; i++)
#pragma unroll
                for (int j = 0; j < 4; j++)
                    accv[i][j] += pv[i] * vv[j];
        }
    }

    if (!isLong) {
        float* obase = out + bh_off + (size_t)qb * BS_ * NC;
#pragma unroll
        for (int i = 0; i < 4; i++) {
            float inv = 1.f / l_i[i];
            float4 o;
            o.x = accv[i][0] * inv; o.y = accv[i][1] * inv;
            o.z = accv[i][2] * inv; o.w = accv[i][3] * inv;
            *(float4*)&obase[(size_t)(r0 + i) * NC + c0] = o;
        }
    } else {
        const int bh8 = ((li * B_ + b) * H_ + h) * NCHUNK + chunk;
        if (tx == 0) {
#pragma unroll
            for (int i = 0; i < 4; i++) {
                g_pm[bh8 * 64 + r0 + i] = m_i[i];
                g_pl[bh8 * 64 + r0 + i] = l_i[i];
            }
        }
#pragma unroll
        for (int i = 0; i < 4; i++) {
            float4 a;
            a.x = accv[i][0]; a.y = accv[i][1];
            a.z = accv[i][2]; a.w = accv[i][3];
            *(float4*)&g_pacc[(size_t)(bh8 * 64 + r0 + i) * 64 + c0] = a;
        }
    }
}

// ---------------------------------------------------------------------------
// Combine split-softmax partials (unchanged).
// ---------------------------------------------------------------------------
__global__ __launch_bounds__(256) void bb_combine(float* __restrict__ out)
{
    const int li = blockIdx.x, h = blockIdx.y, b = blockIdx.z;
    const int t = threadIdx.x;
    const int r = t >> 2;
    const int d0 = (t & 3) * 16;

    const int bhc0 = ((li * B_ + b) * H_ + h) * NCHUNK;

    float m[NCHUNK], w[NCHUNK];
    float M = -INFINITY;
#pragma unroll
    for (int c = 0; c < NCHUNK; c++) {
        m[c] = g_pm[(bhc0 + c) * 64 + r];
        M = fmaxf(M, m[c]);
    }
    float L = 0.f;
#pragma unroll
    for (int c = 0; c < NCHUNK; c++) {
        w[c] = __expf(m[c] - M);
        L += g_pl[(bhc0 + c) * 64 + r] * w[c];
    }
    const float inv = 1.f / L;

    const int qb = li ? (NB_ - 1) : 0;
    float* obase = out + ((size_t)b * S_ + (size_t)qb * BS_ + r) * NC
                       + (size_t)h * D_ + d0;

#pragma unroll
    for (int dd = 0; dd < 16; dd += 4) {
        float4 o; o.x = o.y = o.z = o.w = 0.f;
#pragma unroll
        for (int c = 0; c < NCHUNK; c++) {
            const float4 a = *(const float4*)
                &g_pacc[(size_t)((bhc0 + c) * 64 + r) * 64 + d0 + dd];
            o.x += a.x * w[c]; o.y += a.y * w[c];
            o.z += a.z * w[c]; o.w += a.w * w[c];
        }
        o.x *= inv; o.y *= inv; o.z *= inv; o.w *= inv;
        *(float4*)&obase[dd] = o;
    }
}

// ---------------------------------------------------------------------------
extern "C" void kernel_launch(void* const* d_in, const int* in_sizes, int n_in,
                              void* d_out, int out_size)
{
    const float* x  = (const float*)d_in[0];
    const float* wq = (const float*)d_in[1];
    const float* bq = (const float*)d_in[2];
    const float* wk = (const float*)d_in[3];
    const float* bk = (const float*)d_in[4];
    const float* wv = (const float*)d_in[5];
    const float* bv = (const float*)d_in[6];
    const int* rand_attn = (const int*)d_in[7];
    float* out = (float*)d_out;

    cudaFuncSetAttribute(qkv_mma,
                         cudaFuncAttributeMaxDynamicSharedMemorySize, QKV_SMEM);

    xsplit<<<MROWS * DM_ / (256 * 4), 256>>>(x);
    wsplit<<<dim3(8, 8, 3), 256>>>(wq, wk, wv);
    qkv_mma<<<dim3(4, 64, 3), 256, QKV_SMEM>>>(bq, bk, bv);

    dim3 g2(2 * NCHUNK + (NB_ - 2), H_, B_);
    bigbird_attn<<<g2, 256>>>(rand_attn, out);

    dim3 g3(2, H_, B_);
    bb_combine<<<g3, 256>>>(out);
}